// round 2
// baseline (speedup 1.0000x reference)
#include <cuda_runtime.h>
#include <math.h>

#define R 512
#define KCLS 81
#define NTHREADS 256
#define XFORM_CLIP 4.135166556742356f
#define IMW_M1 1332.0f
#define IMH_M1 799.0f

// Scratch: masked per-(roi, class) scores after NMS.
__device__ float g_dists[R * KCLS];

// ---------------------------------------------------------------------------
// Kernel A: one block per class. Sort, bbox transform, NMS, write masked scores.
// ---------------------------------------------------------------------------
__global__ __launch_bounds__(NTHREADS, 1)
void nms_kernel(const float* __restrict__ rois,
                const float* __restrict__ deltas,
                const float* __restrict__ scores) {
    __shared__ float ss[R];          // sorted scores
    __shared__ int   si[R];          // sorted original indices
    __shared__ float bx1[R], by1[R], bx2[R], by2[R], bar[R];
    __shared__ unsigned sup[R][16];  // suppression bitmask, bits j>i only
    __shared__ unsigned s_keep[16];
    __shared__ float s_red[NTHREADS];

    const int k = blockIdx.x;
    const int tid = threadIdx.x;

    // Load scores for this class; track column max (for cls_valid).
    float m = 0.0f;
    for (int r = tid; r < R; r += NTHREADS) {
        float s = scores[r * KCLS + k];
        ss[r] = s;
        si[r] = r;
        m = fmaxf(m, s);
    }
    s_red[tid] = m;
    __syncthreads();
    for (int off = NTHREADS / 2; off > 0; off >>= 1) {
        if (tid < off) s_red[tid] = fmaxf(s_red[tid], s_red[tid + off]);
        __syncthreads();
    }
    const bool cls_valid = (k >= 1) && (s_red[0] > 0.001f);

    // Bitonic sort of (score, idx): score desc, idx asc on ties
    // (equivalent to stable argsort of -scores).
    for (int kk = 2; kk <= R; kk <<= 1) {
        for (int j = kk >> 1; j > 0; j >>= 1) {
            for (int e = tid; e < R; e += NTHREADS) {
                int p = e ^ j;
                if (p > e) {
                    float sa = ss[e], sb = ss[p];
                    int ia = si[e], ib = si[p];
                    bool aFirst = (sa > sb) || (sa == sb && ia < ib);
                    bool up = ((e & kk) == 0);
                    if (up != aFirst) {
                        ss[e] = sb; ss[p] = sa;
                        si[e] = ib; si[p] = ia;
                    }
                }
            }
            __syncthreads();
        }
    }

    // bbox transform for this class, directly into sorted order.
    for (int i = tid; i < R; i += NTHREADS) {
        int r = si[i];
        float rx1 = rois[r * 4 + 0], ry1 = rois[r * 4 + 1];
        float rx2 = rois[r * 4 + 2], ry2 = rois[r * 4 + 3];
        float w = rx2 - rx1 + 1.0f, h = ry2 - ry1 + 1.0f;
        float cx = rx1 + 0.5f * w, cy = ry1 + 0.5f * h;
        const float* dp = deltas + r * (4 * KCLS) + k * 4;
        float dx = dp[0] / 10.0f;
        float dy = dp[1] / 10.0f;
        float dw = fminf(dp[2] / 5.0f, XFORM_CLIP);
        float dh = fminf(dp[3] / 5.0f, XFORM_CLIP);
        float pcx = dx * w + cx, pcy = dy * h + cy;
        float pw = expf(dw) * w, ph = expf(dh) * h;
        float x1 = fminf(fmaxf(pcx - 0.5f * pw, 0.0f), IMW_M1);
        float y1 = fminf(fmaxf(pcy - 0.5f * ph, 0.0f), IMH_M1);
        float x2 = fminf(fmaxf(pcx + 0.5f * pw - 1.0f, 0.0f), IMW_M1);
        float y2 = fminf(fmaxf(pcy + 0.5f * ph - 1.0f, 0.0f), IMH_M1);
        bx1[i] = x1; by1[i] = y1; bx2[i] = x2; by2[i] = y2;
        bar[i] = (x2 - x1 + 1.0f) * (y2 - y1 + 1.0f);
    }
    __syncthreads();

    // Suppression bitmask: sup[i][w] bit b set iff IoU(i, j=w*32+b) > 0.5, j>i.
    for (int t = tid; t < R * 16; t += NTHREADS) {
        int i = t >> 4;
        int w = t & 15;
        unsigned bits = 0u;
        int jb = w << 5;
        if (jb + 31 > i) {
            float ax1 = bx1[i], ay1 = by1[i], ax2 = bx2[i], ay2 = by2[i];
            float aa = bar[i];
            #pragma unroll 8
            for (int b = 0; b < 32; ++b) {
                int j = jb + b;
                if (j > i) {
                    float xx1 = fmaxf(ax1, bx1[j]);
                    float yy1 = fmaxf(ay1, by1[j]);
                    float xx2 = fminf(ax2, bx2[j]);
                    float yy2 = fminf(ay2, by2[j]);
                    float iw = fmaxf(xx2 - xx1 + 1.0f, 0.0f);
                    float ih = fmaxf(yy2 - yy1 + 1.0f, 0.0f);
                    float inter = iw * ih;
                    float iou = inter / (aa + bar[j] - inter);
                    if (iou > 0.5f) bits |= (1u << b);
                }
            }
        }
        sup[i][w] = bits;
    }
    __syncthreads();

    // Greedy suppression by warp 0. Lane l<16 owns keep word l.
    // Skip directly to the next still-kept index (iterations = #kept).
    if (tid < 32) {
        unsigned keepw = (tid < 16) ? 0xFFFFFFFFu : 0u;
        int i = -1;
        const int lo = tid << 5;
        while (true) {
            unsigned wm = keepw;
            if (tid < 16 && i >= lo) {
                int sh = i - lo;
                wm = (sh >= 31) ? 0u : (wm & ~((2u << sh) - 1u));
            }
            int cand = wm ? (lo + __ffs(wm) - 1) : 1024;
            int nxt = __reduce_min_sync(0xFFFFFFFFu, cand);
            if (nxt >= 1024) break;
            i = nxt;
            if (tid < 16) keepw &= ~sup[i][tid];
        }
        // Cap at POST_NMS_TOPN = 300 (cumsum over sorted order).
        int pc = (tid < 16) ? __popc(keepw) : 0;
        int incl = pc;
        for (int off = 1; off < 32; off <<= 1) {
            int nn = __shfl_up_sync(0xFFFFFFFFu, incl, off);
            if ((int)tid >= off) incl += nn;
        }
        int excl = incl - pc;
        if (tid < 16) {
            if (excl >= 300) {
                keepw = 0u;
            } else {
                int allowed = 300 - excl;
                while (__popc(keepw) > allowed)
                    keepw &= ~(0x80000000u >> __clz(keepw));
            }
            s_keep[tid] = keepw;
        }
    }
    __syncthreads();

    // Scatter masked scores back to original roi order.
    for (int i = tid; i < R; i += NTHREADS) {
        bool kept = (s_keep[i >> 5] >> (i & 31)) & 1u;
        float v = (kept && cls_valid) ? ss[i] : 0.0f;
        g_dists[si[i] * KCLS + k] = v;
    }
}

// ---------------------------------------------------------------------------
// Kernel B: per-roi max/argmax over classes, global sort, top-100, output.
// Output layout (700 floats): [100x5 score+box][100 labels][100 top indices]
// ---------------------------------------------------------------------------
__global__ __launch_bounds__(R, 1)
void select_kernel(const float* __restrict__ rois,
                   const float* __restrict__ deltas,
                   float* __restrict__ out) {
    __shared__ float ps[R];
    __shared__ int   pi[R];
    __shared__ int   plbl[R];
    const int tid = threadIdx.x;

    {
        const float* row = g_dists + tid * KCLS;
        float best = row[0];   // class 0 is always 0 (cls_valid[0] = false)
        int lbl = 0;
        #pragma unroll 8
        for (int k = 1; k < KCLS; ++k) {
            float v = row[k];
            if (v > best) { best = v; lbl = k; }   // first-max == jnp argmax
        }
        ps[tid] = best;
        pi[tid] = tid;
        plbl[tid] = lbl;
    }
    __syncthreads();

    // Bitonic sort: score desc, idx asc on ties (stable-equivalent).
    for (int kk = 2; kk <= R; kk <<= 1) {
        for (int j = kk >> 1; j > 0; j >>= 1) {
            int e = tid, p = e ^ j;
            if (p > e) {
                float sa = ps[e], sb = ps[p];
                int ia = pi[e], ib = pi[p];
                bool aFirst = (sa > sb) || (sa == sb && ia < ib);
                bool up = ((e & kk) == 0);
                if (up != aFirst) {
                    ps[e] = sb; ps[p] = sa;
                    pi[e] = ib; pi[p] = ia;
                }
            }
            __syncthreads();
        }
    }

    if (tid < 100) {
        float sc = ps[tid];
        int r = pi[tid];
        int lbl = plbl[r];
        bool valid = sc > 0.001f;

        // Recompute the selected box (r, lbl).
        float rx1 = rois[r * 4 + 0], ry1 = rois[r * 4 + 1];
        float rx2 = rois[r * 4 + 2], ry2 = rois[r * 4 + 3];
        float w = rx2 - rx1 + 1.0f, h = ry2 - ry1 + 1.0f;
        float cx = rx1 + 0.5f * w, cy = ry1 + 0.5f * h;
        const float* dp = deltas + r * (4 * KCLS) + lbl * 4;
        float dx = dp[0] / 10.0f;
        float dy = dp[1] / 10.0f;
        float dw = fminf(dp[2] / 5.0f, XFORM_CLIP);
        float dh = fminf(dp[3] / 5.0f, XFORM_CLIP);
        float pcx = dx * w + cx, pcy = dy * h + cy;
        float pw = expf(dw) * w, ph = expf(dh) * h;
        float x1 = fminf(fmaxf(pcx - 0.5f * pw, 0.0f), IMW_M1);
        float y1 = fminf(fmaxf(pcy - 0.5f * ph, 0.0f), IMH_M1);
        float x2 = fminf(fmaxf(pcx + 0.5f * pw - 1.0f, 0.0f), IMW_M1);
        float y2 = fminf(fmaxf(pcy + 0.5f * ph - 1.0f, 0.0f), IMH_M1);

        if (!valid) { sc = 0.0f; x1 = 0.0f; y1 = 0.0f; x2 = 0.0f; y2 = 0.0f; }

        out[tid * 5 + 0] = sc;
        out[tid * 5 + 1] = x1;
        out[tid * 5 + 2] = y1;
        out[tid * 5 + 3] = x2;
        out[tid * 5 + 4] = y2;
        out[500 + tid] = (float)lbl;
        out[600 + tid] = (float)r;
    }
}

extern "C" void kernel_launch(void* const* d_in, const int* in_sizes, int n_in,
                              void* d_out, int out_size) {
    const float* rois   = (const float*)d_in[0];
    const float* deltas = (const float*)d_in[1];
    const float* scores = (const float*)d_in[2];
    float* out = (float*)d_out;

    nms_kernel<<<KCLS, NTHREADS>>>(rois, deltas, scores);
    select_kernel<<<1, R>>>(rois, deltas, out);
}

// round 4
// speedup vs baseline: 1.7704x; 1.7704x over previous
#include <cuda_runtime.h>
#include <math.h>

#define R 512
#define KCLS 81
#define NT 512
#define XFORM_CLIP 4.135166556742356f
#define IMW_M1 1332.0f
#define IMH_M1 799.0f

// Scratch: masked per-(class, roi) scores after NMS. Layout [k][r] (transposed
// vs round 1) so select_kernel's per-roi class scan is coalesced.
__device__ float g_dists[KCLS * R];

// ---------------------------------------------------------------------------
// Kernel A: one block per class, 512 threads. Sort, bbox transform, NMS,
// write masked scores. Thread t owns sorted column j=t with its box in
// registers; row boxes are broadcast LDS (conflict-free); suppression bits
// assembled via ballot.
// ---------------------------------------------------------------------------
__global__ __launch_bounds__(NT, 1)
void nms_kernel(const float* __restrict__ rois,
                const float* __restrict__ deltas,
                const float* __restrict__ scores) {
    __shared__ float  ss[R];           // sorted scores
    __shared__ int    si[R];           // sorted original indices
    __shared__ float4 sb[R];           // sorted boxes (x1,y1,x2,y2)
    __shared__ float  sar[R];          // areas
    __shared__ unsigned sup[R][16];    // suppression bitmask, bits j>i only
    __shared__ unsigned s_keep[16];
    __shared__ float  s_red[32];

    const int k    = blockIdx.x;
    const int tid  = threadIdx.x;
    const int lane = tid & 31;
    const int wid  = tid >> 5;

    // Zero the suppression mask (rows beyond each warp's triangle stay 0).
    {
        unsigned* p = &sup[0][0];
        #pragma unroll
        for (int t = tid; t < R * 16; t += NT) p[t] = 0u;
    }

    // Load this class's score; block max for cls_valid.
    float s = scores[tid * KCLS + k];
    ss[tid] = s;
    si[tid] = tid;
    {
        float m = s;
        #pragma unroll
        for (int o = 16; o > 0; o >>= 1)
            m = fmaxf(m, __shfl_xor_sync(0xFFFFFFFFu, m, o));
        if (lane == 0) s_red[wid] = m;
    }
    __syncthreads();
    if (wid == 0) {
        float v = (lane < 16) ? s_red[lane] : 0.0f;
        #pragma unroll
        for (int o = 8; o > 0; o >>= 1)
            v = fmaxf(v, __shfl_xor_sync(0xFFFFFFFFu, v, o));
        if (lane == 0) s_red[0] = v;
    }
    // (visible after the sort's barriers; read at the very end)

    // Bitonic sort of (score, idx): score desc, idx asc on ties
    // (stable-equivalent to jnp.argsort(-scores)).
    for (int kk = 2; kk <= R; kk <<= 1) {
        for (int j = kk >> 1; j > 0; j >>= 1) {
            int p = tid ^ j;
            if (p > tid) {
                float sa = ss[tid], sb_ = ss[p];
                int ia = si[tid], ib = si[p];
                bool aFirst = (sa > sb_) || (sa == sb_ && ia < ib);
                bool up = ((tid & kk) == 0);
                if (up != aFirst) {
                    ss[tid] = sb_; ss[p] = sa;
                    si[tid] = ib;  si[p] = ia;
                }
            }
            __syncthreads();
        }
    }

    // bbox transform: thread t computes the box at sorted position t.
    // Keep it in registers (it is this thread's j-column box) AND in smem.
    float jx1, jy1, jx2, jy2, jar;
    {
        int r = si[tid];
        float rx1 = rois[r * 4 + 0], ry1 = rois[r * 4 + 1];
        float rx2 = rois[r * 4 + 2], ry2 = rois[r * 4 + 3];
        float w = rx2 - rx1 + 1.0f, h = ry2 - ry1 + 1.0f;
        float cx = rx1 + 0.5f * w, cy = ry1 + 0.5f * h;
        const float* dp = deltas + r * (4 * KCLS) + k * 4;
        float dx = dp[0] / 10.0f;
        float dy = dp[1] / 10.0f;
        float dw = fminf(dp[2] / 5.0f, XFORM_CLIP);
        float dh = fminf(dp[3] / 5.0f, XFORM_CLIP);
        float pcx = dx * w + cx, pcy = dy * h + cy;
        float pw = expf(dw) * w, ph = expf(dh) * h;
        jx1 = fminf(fmaxf(pcx - 0.5f * pw, 0.0f), IMW_M1);
        jy1 = fminf(fmaxf(pcy - 0.5f * ph, 0.0f), IMH_M1);
        jx2 = fminf(fmaxf(pcx + 0.5f * pw - 1.0f, 0.0f), IMW_M1);
        jy2 = fminf(fmaxf(pcy + 0.5f * ph - 1.0f, 0.0f), IMH_M1);
        jar = (jx2 - jx1 + 1.0f) * (jy2 - jy1 + 1.0f);
        sb[tid]  = make_float4(jx1, jy1, jx2, jy2);
        sar[tid] = jar;
    }
    __syncthreads();

    // Suppression mask build. Warp w owns columns j in [w*32, w*32+32); only
    // rows i < w*32+31 can have j>i bits. Row box via broadcast LDS128.
    {
        const int j = tid;
        const int imax = (wid << 5) + 31;   // exclusive bound (min with R implied: wid<16)
        for (int i = 0; i < imax; ++i) {
            float4 b = sb[i];
            float aa = sar[i];
            float xx1 = fmaxf(b.x, jx1);
            float yy1 = fmaxf(b.y, jy1);
            float xx2 = fminf(b.z, jx2);
            float yy2 = fminf(b.w, jy2);
            float iw = fmaxf(xx2 - xx1 + 1.0f, 0.0f);
            float ih = fmaxf(yy2 - yy1 + 1.0f, 0.0f);
            float inter = iw * ih;
            float iou = inter / (aa + jar - inter);
            bool ov = (iou > 0.5f) && (j > i);
            unsigned bits = __ballot_sync(0xFFFFFFFFu, ov);
            if (lane == 0) sup[i][wid] = bits;
        }
    }
    __syncthreads();

    // Greedy suppression by warp 0. Lane l<16 owns keep word l.
    // Skip directly to the next still-kept index (iterations = #kept).
    if (tid < 32) {
        unsigned keepw = (tid < 16) ? 0xFFFFFFFFu : 0u;
        int i = -1;
        const int lo = tid << 5;
        while (true) {
            unsigned wm = keepw;
            if (tid < 16 && i >= lo) {
                int sh = i - lo;
                wm = (sh >= 31) ? 0u : (wm & ~((2u << sh) - 1u));
            }
            int cand = wm ? (lo + __ffs(wm) - 1) : 1024;
            int nxt = __reduce_min_sync(0xFFFFFFFFu, cand);
            if (nxt >= 1024) break;
            i = nxt;
            if (tid < 16) keepw &= ~sup[i][tid];
        }
        // Cap at POST_NMS_TOPN = 300 (cumsum over sorted order).
        int pc = (tid < 16) ? __popc(keepw) : 0;
        int incl = pc;
        #pragma unroll
        for (int off = 1; off < 32; off <<= 1) {
            int nn = __shfl_up_sync(0xFFFFFFFFu, incl, off);
            if ((int)tid >= off) incl += nn;
        }
        int excl = incl - pc;
        if (tid < 16) {
            if (excl >= 300) {
                keepw = 0u;
            } else {
                int allowed = 300 - excl;
                while (__popc(keepw) > allowed)
                    keepw &= ~(0x80000000u >> __clz(keepw));
            }
            s_keep[tid] = keepw;
        }
    }
    __syncthreads();

    // Scatter masked scores, transposed layout [k][r].
    {
        const bool cls_valid = (k >= 1) && (s_red[0] > 0.001f);
        bool kept = (s_keep[tid >> 5] >> (tid & 31)) & 1u;
        g_dists[k * R + si[tid]] = (kept && cls_valid) ? ss[tid] : 0.0f;
    }
}

// ---------------------------------------------------------------------------
// Kernel B: per-roi max/argmax over classes (coalesced), global sort, top-100.
// Output layout (700 floats): [100x5 score+box][100 labels][100 top indices]
// ---------------------------------------------------------------------------
__global__ __launch_bounds__(R, 1)
void select_kernel(const float* __restrict__ rois,
                   const float* __restrict__ deltas,
                   float* __restrict__ out) {
    __shared__ float ps[R];
    __shared__ int   pi[R];
    __shared__ int   plbl[R];
    const int tid = threadIdx.x;

    {
        float best = g_dists[0 * R + tid];   // class 0 column is always 0
        int lbl = 0;
        #pragma unroll
        for (int k = 1; k < KCLS; ++k) {
            float v = g_dists[k * R + tid];
            if (v > best) { best = v; lbl = k; }   // first-max == jnp argmax
        }
        ps[tid] = best;
        pi[tid] = tid;
        plbl[tid] = lbl;
    }
    __syncthreads();

    // Bitonic sort: score desc, idx asc on ties (stable-equivalent).
    for (int kk = 2; kk <= R; kk <<= 1) {
        for (int j = kk >> 1; j > 0; j >>= 1) {
            int e = tid, p = e ^ j;
            if (p > e) {
                float sa = ps[e], sb = ps[p];
                int ia = pi[e], ib = pi[p];
                bool aFirst = (sa > sb) || (sa == sb && ia < ib);
                bool up = ((e & kk) == 0);
                if (up != aFirst) {
                    ps[e] = sb; ps[p] = sa;
                    pi[e] = ib; pi[p] = ia;
                }
            }
            __syncthreads();
        }
    }

    if (tid < 100) {
        float sc = ps[tid];
        int r = pi[tid];
        int lbl = plbl[r];
        bool valid = sc > 0.001f;

        // Recompute the selected box (r, lbl).
        float rx1 = rois[r * 4 + 0], ry1 = rois[r * 4 + 1];
        float rx2 = rois[r * 4 + 2], ry2 = rois[r * 4 + 3];
        float w = rx2 - rx1 + 1.0f, h = ry2 - ry1 + 1.0f;
        float cx = rx1 + 0.5f * w, cy = ry1 + 0.5f * h;
        const float* dp = deltas + r * (4 * KCLS) + lbl * 4;
        float dx = dp[0] / 10.0f;
        float dy = dp[1] / 10.0f;
        float dw = fminf(dp[2] / 5.0f, XFORM_CLIP);
        float dh = fminf(dp[3] / 5.0f, XFORM_CLIP);
        float pcx = dx * w + cx, pcy = dy * h + cy;
        float pw = expf(dw) * w, ph = expf(dh) * h;
        float x1 = fminf(fmaxf(pcx - 0.5f * pw, 0.0f), IMW_M1);
        float y1 = fminf(fmaxf(pcy - 0.5f * ph, 0.0f), IMH_M1);
        float x2 = fminf(fmaxf(pcx + 0.5f * pw - 1.0f, 0.0f), IMW_M1);
        float y2 = fminf(fmaxf(pcy + 0.5f * ph - 1.0f, 0.0f), IMH_M1);

        if (!valid) { sc = 0.0f; x1 = 0.0f; y1 = 0.0f; x2 = 0.0f; y2 = 0.0f; }

        out[tid * 5 + 0] = sc;
        out[tid * 5 + 1] = x1;
        out[tid * 5 + 2] = y1;
        out[tid * 5 + 3] = x2;
        out[tid * 5 + 4] = y2;
        out[500 + tid] = (float)lbl;
        out[600 + tid] = (float)r;
    }
}

extern "C" void kernel_launch(void* const* d_in, const int* in_sizes, int n_in,
                              void* d_out, int out_size) {
    const float* rois   = (const float*)d_in[0];
    const float* deltas = (const float*)d_in[1];
    const float* scores = (const float*)d_in[2];
    float* out = (float*)d_out;

    nms_kernel<<<KCLS, NT>>>(rois, deltas, scores);
    select_kernel<<<1, R>>>(rois, deltas, out);
}

// round 6
// speedup vs baseline: 3.6009x; 2.0339x over previous
#include <cuda_runtime.h>
#include <math.h>

#define R 512
#define KCLS 81
#define NT 512
#define XFORM_CLIP 4.135166556742356f
#define IMW_M1 1332.0f
#define IMH_M1 799.0f
#define INIT_KEY 0x00000000FFFFFFFFull

// Cross-block state (persistent __device__ globals; reset each call by the
// select block under the flag/counter protocol).
__device__ unsigned long long g_keys[R];
__device__ int g_flag;   // zero-init: select block has reset g_keys
__device__ int g_ctr;    // zero-init: number of finished nms blocks

__device__ __forceinline__ void bbox_xform(const float* __restrict__ rois,
                                           const float* __restrict__ deltas,
                                           int r, int k,
                                           float& x1, float& y1,
                                           float& x2, float& y2) {
    float rx1 = rois[r * 4 + 0], ry1 = rois[r * 4 + 1];
    float rx2 = rois[r * 4 + 2], ry2 = rois[r * 4 + 3];
    float w = rx2 - rx1 + 1.0f, h = ry2 - ry1 + 1.0f;
    float cx = rx1 + 0.5f * w, cy = ry1 + 0.5f * h;
    const float* dp = deltas + r * (4 * KCLS) + k * 4;
    float dx = dp[0] / 10.0f;
    float dy = dp[1] / 10.0f;
    float dw = fminf(dp[2] / 5.0f, XFORM_CLIP);
    float dh = fminf(dp[3] / 5.0f, XFORM_CLIP);
    float pcx = dx * w + cx, pcy = dy * h + cy;
    float pw = expf(dw) * w, ph = expf(dh) * h;
    x1 = fminf(fmaxf(pcx - 0.5f * pw, 0.0f), IMW_M1);
    y1 = fminf(fmaxf(pcy - 0.5f * ph, 0.0f), IMH_M1);
    x2 = fminf(fmaxf(pcx + 0.5f * pw - 1.0f, 0.0f), IMW_M1);
    y2 = fminf(fmaxf(pcy + 0.5f * ph - 1.0f, 0.0f), IMH_M1);
}

__global__ __launch_bounds__(NT, 1)
void fused_kernel(const float* __restrict__ rois,
                  const float* __restrict__ deltas,
                  const float* __restrict__ scores,
                  float* __restrict__ out) {
    __shared__ float    ss[R];
    __shared__ int      si[R];
    __shared__ float4   sb[R];
    __shared__ float    sar[R];
    __shared__ unsigned sup[R][16];
    __shared__ unsigned s_keep[16];
    __shared__ float    s_red[32];

    const int tid  = threadIdx.x;
    const int lane = tid & 31;
    const int wid  = tid >> 5;
    const int bid  = blockIdx.x;

    if (bid < KCLS) {
        // ============================ NMS block (one class) =================
        const int k = bid;

        // Zero suppression mask.
        {
            unsigned* p = &sup[0][0];
            #pragma unroll
            for (int t = tid; t < R * 16; t += NT) p[t] = 0u;
        }

        // Load this class's scores; block max for cls_valid.
        float s = scores[tid * KCLS + k];
        ss[tid] = s;
        si[tid] = tid;
        {
            float m = s;
            #pragma unroll
            for (int o = 16; o > 0; o >>= 1)
                m = fmaxf(m, __shfl_xor_sync(0xFFFFFFFFu, m, o));
            if (lane == 0) s_red[wid] = m;
        }
        __syncthreads();
        if (wid == 0) {
            float v = (lane < 16) ? s_red[lane] : 0.0f;
            #pragma unroll
            for (int o = 8; o > 0; o >>= 1)
                v = fmaxf(v, __shfl_xor_sync(0xFFFFFFFFu, v, o));
            if (lane == 0) s_red[0] = v;
        }
        __syncthreads();
        const bool cls_valid = (k >= 1) && (s_red[0] > 0.001f);
        if (!cls_valid) {
            // Nothing to contribute; just count in.
            if (tid == 0) { __threadfence(); atomicAdd(&g_ctr, 1); }
            return;
        }

        // Bitonic sort (score desc, idx asc on ties) == stable argsort(-s).
        for (int kk = 2; kk <= R; kk <<= 1) {
            for (int j = kk >> 1; j > 0; j >>= 1) {
                int p = tid ^ j;
                if (p > tid) {
                    float sa = ss[tid], sb_ = ss[p];
                    int ia = si[tid], ib = si[p];
                    bool aFirst = (sa > sb_) || (sa == sb_ && ia < ib);
                    bool up = ((tid & kk) == 0);
                    if (up != aFirst) {
                        ss[tid] = sb_; ss[p] = sa;
                        si[tid] = ib;  si[p] = ia;
                    }
                }
                __syncthreads();
            }
        }

        // bbox transform at sorted position tid.
        {
            float x1, y1, x2, y2;
            bbox_xform(rois, deltas, si[tid], k, x1, y1, x2, y2);
            sb[tid]  = make_float4(x1, y1, x2, y2);
            sar[tid] = (x2 - x1 + 1.0f) * (y2 - y1 + 1.0f);
        }
        __syncthreads();

        // Suppression mask build, load-balanced over the j>i triangle.
        // Work items t enumerate (column-word jw, row i) pairs with
        // i < 32*jw+31; prefix S(jw) = 16*jw^2 + 15*jw, total 4336.
        {
            int t  = wid * 271;
            int t1 = min(t + 271, 4336);
            int jw = 0, Sc = 0, Sn = 31;
            while (Sn <= t) {
                jw++; Sc = Sn; Sn = 16 * (jw + 1) * (jw + 1) + 15 * (jw + 1);
            }
            float4 jb   = sb[(jw << 5) + lane];
            float jarea = sar[(jw << 5) + lane];
            int   j     = (jw << 5) + lane;
            for (; t < t1; ++t) {
                if (t == Sn) {
                    jw++; Sc = Sn; Sn = 16 * (jw + 1) * (jw + 1) + 15 * (jw + 1);
                    jb = sb[(jw << 5) + lane];
                    jarea = sar[(jw << 5) + lane];
                    j = (jw << 5) + lane;
                }
                int i = t - Sc;
                float4 b = sb[i];          // broadcast LDS128 (conflict-free)
                float aa = sar[i];
                float xx1 = fmaxf(b.x, jb.x);
                float yy1 = fmaxf(b.y, jb.y);
                float xx2 = fminf(b.z, jb.z);
                float yy2 = fminf(b.w, jb.w);
                float iw = fmaxf(xx2 - xx1 + 1.0f, 0.0f);
                float ih = fmaxf(yy2 - yy1 + 1.0f, 0.0f);
                float inter = iw * ih;
                float sum2  = aa + jarea;
                bool ov = false;
                // Conservative pre-filter: exact iou>0.5 requires
                // 3*inter > sum2; the 0.999 margin absorbs all fp rounding,
                // so skipping the division here can never flip the result.
                if (3.0f * inter > 0.999f * sum2) {
                    float iou = inter / (sum2 - inter);   // exact div.rn as ref
                    ov = (iou > 0.5f);
                }
                ov = ov && (j > i);
                unsigned bits = __ballot_sync(0xFFFFFFFFu, ov);
                if (lane == 0) sup[i][jw] = bits;
            }
        }
        __syncthreads();

        // Greedy suppression (warp 0), skip-to-next-kept; early stop at 300
        // kept (POST_NMS_TOPN drops everything after the 300th anyway).
        if (tid < 32) {
            unsigned keepw = (tid < 16) ? 0xFFFFFFFFu : 0u;
            int i = -1, cnt = 0;
            const int lo = tid << 5;
            while (true) {
                unsigned wm = keepw;
                if (i >= lo) {
                    int sh = i - lo;
                    wm = (sh >= 31) ? 0u : (wm & ~((2u << sh) - 1u));
                }
                int cand = wm ? (lo + __ffs(wm) - 1) : 1024;
                int nxt = __reduce_min_sync(0xFFFFFFFFu, cand);
                if (nxt >= 1024) break;
                i = nxt;
                if (tid < 16) keepw &= ~sup[i][tid];
                if (++cnt == 300) {
                    if (lo > i)            keepw = 0u;
                    else if (i < lo + 32)  keepw &= ((2u << (i - lo)) - 1u);
                    break;
                }
            }
            if (tid < 16) s_keep[tid] = keepw;
        }
        __syncthreads();

        // Fold kept scores into global per-roi argmax keys.
        // Key = (score_bits << 32) | (~class): max score wins, ties -> lowest
        // class; the init key (score=0, class=0) reproduces the all-zero row.
        if (tid == 0) {
            while (*(volatile int*)&g_flag == 0) {}   // wait for key reset
        }
        __syncthreads();
        __threadfence();
        {
            bool kept = (s_keep[tid >> 5] >> (tid & 31)) & 1u;
            if (kept) {
                unsigned long long key =
                    ((unsigned long long)__float_as_uint(ss[tid]) << 32) |
                    (unsigned long long)(0xFFFFFFFFu - (unsigned)k);
                atomicMax(&g_keys[si[tid]], key);
            }
        }
        __threadfence();
        __syncthreads();
        if (tid == 0) atomicAdd(&g_ctr, 1);

    } else {
        // ============================ Select block ==========================
        // Reset keys, then open the gate for the nms blocks' atomicMax.
        g_keys[tid] = INIT_KEY;
        __threadfence();
        __syncthreads();
        if (tid == 0) *(volatile int*)&g_flag = 1;

        // Wait until all 81 classes have folded in.
        if (tid == 0) {
            while (*(volatile int*)&g_ctr < KCLS) {}
        }
        __syncthreads();
        __threadfence();

        float* ps   = ss;
        int*   pi   = si;
        int*   plbl = (int*)&sup[0][0];

        {
            unsigned long long key = *(volatile unsigned long long*)&g_keys[tid];
            float sc = __uint_as_float((unsigned)(key >> 32));
            int lbl  = (int)(0xFFFFFFFFu - (unsigned)(key & 0xFFFFFFFFull));
            ps[tid] = sc;
            pi[tid] = tid;
            plbl[tid] = lbl;
        }
        __syncthreads();

        // Bitonic sort: score desc, idx asc on ties (stable-equivalent).
        for (int kk = 2; kk <= R; kk <<= 1) {
            for (int j = kk >> 1; j > 0; j >>= 1) {
                int e = tid, p = e ^ j;
                if (p > e) {
                    float sa = ps[e], sb_ = ps[p];
                    int ia = pi[e], ib = pi[p];
                    bool aFirst = (sa > sb_) || (sa == sb_ && ia < ib);
                    bool up = ((e & kk) == 0);
                    if (up != aFirst) {
                        ps[e] = sb_; ps[p] = sa;
                        pi[e] = ib;  pi[p] = ia;
                    }
                }
                __syncthreads();
            }
        }

        if (tid < 100) {
            float sc = ps[tid];
            int r   = pi[tid];
            int lbl = plbl[r];
            bool valid = sc > 0.001f;

            float x1, y1, x2, y2;
            bbox_xform(rois, deltas, r, lbl, x1, y1, x2, y2);

            if (!valid) { sc = 0.0f; x1 = 0.0f; y1 = 0.0f; x2 = 0.0f; y2 = 0.0f; }

            out[tid * 5 + 0] = sc;
            out[tid * 5 + 1] = x1;
            out[tid * 5 + 2] = y1;
            out[tid * 5 + 3] = x2;
            out[tid * 5 + 4] = y2;
            out[500 + tid] = (float)lbl;
            out[600 + tid] = (float)r;
        }
        __syncthreads();
        if (tid == 0) { g_ctr = 0; g_flag = 0; }   // rearm for next replay
    }
}

extern "C" void kernel_launch(void* const* d_in, const int* in_sizes, int n_in,
                              void* d_out, int out_size) {
    const float* rois   = (const float*)d_in[0];
    const float* deltas = (const float*)d_in[1];
    const float* scores = (const float*)d_in[2];
    float* out = (float*)d_out;

    fused_kernel<<<KCLS + 1, NT>>>(rois, deltas, scores, out);
}

// round 7
// speedup vs baseline: 6.0300x; 1.6746x over previous
#include <cuda_runtime.h>
#include <math.h>

#define R 512
#define KCLS 81
#define NT 512
#define XFORM_CLIP 4.135166556742356f
#define IMW_M1 1332.0f
#define IMH_M1 799.0f
#define INIT_KEY 0x00000000FFFFFFFFull
// iou>0.5 <=> inter/(sum2-inter)>0.5 <=> inter>sum2/3. Certain-yes / certain-no
// thresholds with ~1e-3 margin (fp rounding of the whole ref chain is <3e-7):
#define C_HI 0.33350f
#define C_LO 0.33317f

// Cross-block state (persistent __device__ globals; reset each call by the
// select block under the flag/counter protocol).
__device__ unsigned long long g_keys[R];
__device__ int g_flag;   // 1 => select block has reset g_keys
__device__ int g_ctr;    // number of finished nms blocks

__device__ __forceinline__ void bbox_xform(const float* __restrict__ rois,
                                           const float* __restrict__ deltas,
                                           int r, int k,
                                           float& x1, float& y1,
                                           float& x2, float& y2) {
    float rx1 = rois[r * 4 + 0], ry1 = rois[r * 4 + 1];
    float rx2 = rois[r * 4 + 2], ry2 = rois[r * 4 + 3];
    float w = rx2 - rx1 + 1.0f, h = ry2 - ry1 + 1.0f;
    float cx = rx1 + 0.5f * w, cy = ry1 + 0.5f * h;
    const float* dp = deltas + r * (4 * KCLS) + k * 4;
    float dx = dp[0] / 10.0f;
    float dy = dp[1] / 10.0f;
    float dw = fminf(dp[2] / 5.0f, XFORM_CLIP);
    float dh = fminf(dp[3] / 5.0f, XFORM_CLIP);
    float pcx = dx * w + cx, pcy = dy * h + cy;
    float pw = expf(dw) * w, ph = expf(dh) * h;
    x1 = fminf(fmaxf(pcx - 0.5f * pw, 0.0f), IMW_M1);
    y1 = fminf(fmaxf(pcy - 0.5f * ph, 0.0f), IMH_M1);
    x2 = fminf(fmaxf(pcx + 0.5f * pw - 1.0f, 0.0f), IMW_M1);
    y2 = fminf(fmaxf(pcy + 0.5f * ph - 1.0f, 0.0f), IMH_M1);
}

// Hybrid bitonic sort of 512 (score desc, idx asc on ties). Values live in
// registers; smem arrays are scratch for the 10 cross-warp stages only.
__device__ __forceinline__ void bitonic_sort_512(float& rs, int& ri,
                                                 float* ss, int* si, int tid) {
    #pragma unroll
    for (int kk = 2; kk <= R; kk <<= 1) {
        int j = kk >> 1;
        for (; j >= 32; j >>= 1) {          // cross-warp: via smem
            ss[tid] = rs; si[tid] = ri;
            __syncthreads();
            int p = tid ^ j;
            float os = ss[p]; int oi = si[p];
            bool mineFirst = (rs > os) || (rs == os && ri < oi);
            bool up = ((tid & kk) == 0);
            bool iAmLow = ((tid & j) == 0);
            bool keepMine = (up == iAmLow) ? mineFirst : !mineFirst;
            if (!keepMine) { rs = os; ri = oi; }
            __syncthreads();
        }
        for (; j > 0; j >>= 1) {            // in-warp: via shfl
            float os = __shfl_xor_sync(0xFFFFFFFFu, rs, j);
            int   oi = __shfl_xor_sync(0xFFFFFFFFu, ri, j);
            bool mineFirst = (rs > os) || (rs == os && ri < oi);
            bool up = ((tid & kk) == 0);
            bool iAmLow = ((tid & j) == 0);
            bool keepMine = (up == iAmLow) ? mineFirst : !mineFirst;
            if (!keepMine) { rs = os; ri = oi; }
        }
    }
}

__global__ __launch_bounds__(NT, 1)
void fused_kernel(const float* __restrict__ rois,
                  const float* __restrict__ deltas,
                  const float* __restrict__ scores,
                  float* __restrict__ out) {
    __shared__ float    ss[R];
    __shared__ int      si[R];
    __shared__ float4   sb[R];
    __shared__ float    sar[R];
    __shared__ unsigned sup[R][16];
    __shared__ unsigned s_keep[16];
    __shared__ unsigned unc_flag[16];   // bit r&31 of word r>>5: row r has band pairs
    __shared__ float    s_red[32];

    const int tid  = threadIdx.x;
    const int lane = tid & 31;
    const int wid  = tid >> 5;
    const int bid  = blockIdx.x;

    if (bid < KCLS) {
        // ============================ NMS block (one class) =================
        const int k = bid;

        // Zero suppression mask + flags.
        {
            unsigned* p = &sup[0][0];
            #pragma unroll
            for (int t = tid; t < R * 16; t += NT) p[t] = 0u;
            if (tid < 16) unc_flag[tid] = 0u;
        }

        // Load this class's scores; block max for cls_valid.
        float rs = scores[tid * KCLS + k];
        int   ri = tid;
        {
            float m = rs;
            #pragma unroll
            for (int o = 16; o > 0; o >>= 1)
                m = fmaxf(m, __shfl_xor_sync(0xFFFFFFFFu, m, o));
            if (lane == 0) s_red[wid] = m;
        }
        __syncthreads();
        if (wid == 0) {
            float v = (lane < 16) ? s_red[lane] : 0.0f;
            #pragma unroll
            for (int o = 8; o > 0; o >>= 1)
                v = fmaxf(v, __shfl_xor_sync(0xFFFFFFFFu, v, o));
            if (lane == 0) s_red[0] = v;
        }
        __syncthreads();
        const bool cls_valid = (k >= 1) && (s_red[0] > 0.001f);
        if (!cls_valid) {
            if (tid == 0) { __threadfence(); atomicAdd(&g_ctr, 1); }
            return;
        }

        // Sort (score desc, idx asc) == stable argsort(-scores).
        bitonic_sort_512(rs, ri, ss, si, tid);

        // bbox transform at sorted position tid (box kept in smem for pairs).
        {
            float x1, y1, x2, y2;
            bbox_xform(rois, deltas, ri, k, x1, y1, x2, y2);
            sb[tid]  = make_float4(x1, y1, x2, y2);
            sar[tid] = (x2 - x1 + 1.0f) * (y2 - y1 + 1.0f);
        }
        __syncthreads();

        // ---- Suppression mask build: branch-free, division-free hot loop.
        // Flattened (word jw, row i) triangle, 271 items per warp.
        unsigned myflags = 0u;   // lane l accumulates band-flag bits for rows 32l..32l+31
        {
            int t  = wid * 271;
            int t1 = t + 271;    // wid=15 -> 4336 exactly
            int jw = 0;
            while (16 * (jw + 1) * (jw + 1) + 15 * (jw + 1) <= t) jw++;
            int i = t - (16 * jw * jw + 15 * jw);
            while (t < t1) {
                const int rows = (jw << 5) + 31;
                const int iend = min(rows, i + (t1 - t));
                const int j = (jw << 5) + lane;
                const float4 jb = sb[j];
                const float jarea = sar[j];
                t += iend - i;
                for (; i < iend; ++i) {
                    float4 b = sb[i];            // broadcast LDS128
                    float aa = sar[i];
                    float xx1 = fmaxf(b.x, jb.x);
                    float yy1 = fmaxf(b.y, jb.y);
                    float xx2 = fminf(b.z, jb.z);
                    float yy2 = fminf(b.w, jb.w);
                    float iw = fmaxf(xx2 - xx1 + 1.0f, 0.0f);
                    float ih = fmaxf(yy2 - yy1 + 1.0f, 0.0f);
                    float inter = iw * ih;
                    float sum2  = aa + jarea;
                    bool jgt = (j > i);
                    bool p_yes  = (inter > C_HI * sum2) && jgt;
                    bool p_wide = (inter > C_LO * sum2) && jgt;
                    unsigned b_yes  = __ballot_sync(0xFFFFFFFFu, p_yes);
                    unsigned b_wide = __ballot_sync(0xFFFFFFFFu, p_wide);
                    unsigned b_unc  = b_wide ^ b_yes;
                    if (lane == 0) sup[i][jw] = b_wide;
                    unsigned rowbit = (lane == (i >> 5)) ? (1u << (i & 31)) : 0u;
                    myflags |= b_unc ? rowbit : 0u;
                }
                jw++; i = 0;
            }
        }
        if (lane < 16) atomicOr(&unc_flag[lane], myflags);
        __syncthreads();

        // ---- Exact fixup of band rows (expected ~0-3 rows): recompute the
        // whole row with the reference's exact div.rn semantics.
        {
            unsigned f = unc_flag[wid];
            while (f) {
                int b = __ffs(f) - 1; f &= f - 1;
                int i = (wid << 5) + b;
                float4 bi = sb[i]; float ai = sar[i];
                for (int jw2 = 0; jw2 < 16; ++jw2) {
                    int j = (jw2 << 5) + lane;
                    float4 jb = sb[j];
                    float xx1 = fmaxf(bi.x, jb.x);
                    float yy1 = fmaxf(bi.y, jb.y);
                    float xx2 = fminf(bi.z, jb.z);
                    float yy2 = fminf(bi.w, jb.w);
                    float iw = fmaxf(xx2 - xx1 + 1.0f, 0.0f);
                    float ih = fmaxf(yy2 - yy1 + 1.0f, 0.0f);
                    float inter = iw * ih;
                    float denom = (ai + sar[j]) - inter;
                    float iou = inter / denom;            // exact div.rn
                    bool ov = (iou > 0.5f) && (j > i);
                    unsigned bits = __ballot_sync(0xFFFFFFFFu, ov);
                    if (lane == 0) sup[i][jw2] = bits;
                }
            }
        }
        __syncthreads();

        // ---- Word-phase greedy (warp 0). All lanes track word w's live bits
        // via broadcast LDS; chain per kept box ~ ffs + LDS only.
        if (wid == 0) {
            unsigned keepw = (lane < 16) ? 0xFFFFFFFFu : 0u;
            int cnt = 0;
            bool capped = false;
            for (int w = 0; w < 16 && !capped; ++w) {
                unsigned bw = __shfl_sync(0xFFFFFFFFu, keepw, w);
                while (bw) {
                    int b = __ffs(bw) - 1;
                    int i = (w << 5) + b;
                    cnt++;
                    if (cnt == 300) {   // POST_NMS_TOPN: keep first 300 kept
                        if (lane < 16 && lane > w) keepw = 0u;
                        if (lane == w) keepw &= ((2u << b) - 1u);
                        capped = true;
                        break;
                    }
                    unsigned srl = sup[i][lane & 15];  // per-lane word
                    unsigned srw = sup[i][w];          // broadcast word w
                    if (lane < 16) keepw &= ~srl;
                    bw = (bw ^ (1u << b)) & ~srw;
                }
            }
            if (lane < 16) s_keep[lane] = keepw;
        }
        __syncthreads();

        // ---- Fold kept scores into global per-roi argmax keys.
        if (tid == 0) {
            while (*(volatile int*)&g_flag == 0) {}
        }
        __syncthreads();
        __threadfence();
        {
            bool kept = (s_keep[tid >> 5] >> (tid & 31)) & 1u;
            if (kept) {
                unsigned long long key =
                    ((unsigned long long)__float_as_uint(rs) << 32) |
                    (unsigned long long)(0xFFFFFFFFu - (unsigned)k);
                atomicMax(&g_keys[ri], key);
            }
        }
        __threadfence();
        __syncthreads();
        if (tid == 0) atomicAdd(&g_ctr, 1);

    } else {
        // ============================ Select block ==========================
        g_keys[tid] = INIT_KEY;
        __threadfence();
        __syncthreads();
        if (tid == 0) *(volatile int*)&g_flag = 1;

        if (tid == 0) {
            while (*(volatile int*)&g_ctr < KCLS) {}
        }
        __syncthreads();
        __threadfence();

        int* plbl = (int*)sb;   // sb unused in this block

        float rs; int ri;
        {
            unsigned long long key = *(volatile unsigned long long*)&g_keys[tid];
            rs = __uint_as_float((unsigned)(key >> 32));
            plbl[tid] = (int)(0xFFFFFFFFu - (unsigned)(key & 0xFFFFFFFFull));
            ri = tid;
        }
        __syncthreads();

        bitonic_sort_512(rs, ri, ss, si, tid);

        if (tid < 100) {
            float sc = rs;
            int r   = ri;
            int lbl = plbl[r];
            bool valid = sc > 0.001f;

            float x1, y1, x2, y2;
            bbox_xform(rois, deltas, r, lbl, x1, y1, x2, y2);

            if (!valid) { sc = 0.0f; x1 = 0.0f; y1 = 0.0f; x2 = 0.0f; y2 = 0.0f; }

            out[tid * 5 + 0] = sc;
            out[tid * 5 + 1] = x1;
            out[tid * 5 + 2] = y1;
            out[tid * 5 + 3] = x2;
            out[tid * 5 + 4] = y2;
            out[500 + tid] = (float)lbl;
            out[600 + tid] = (float)r;
        }
        __syncthreads();
        if (tid == 0) { g_ctr = 0; g_flag = 0; }   // rearm for next replay
    }
}

extern "C" void kernel_launch(void* const* d_in, const int* in_sizes, int n_in,
                              void* d_out, int out_size) {
    const float* rois   = (const float*)d_in[0];
    const float* deltas = (const float*)d_in[1];
    const float* scores = (const float*)d_in[2];
    float* out = (float*)d_out;

    fused_kernel<<<KCLS + 1, NT>>>(rois, deltas, scores, out);
}

// round 8
// speedup vs baseline: 6.4320x; 1.0667x over previous
#include <cuda_runtime.h>
#include <math.h>

#define R 512
#define KCLS 81
#define XFORM_CLIP 4.135166556742356f
#define IMW_M1 1332.0f
#define IMH_M1 799.0f
#define INIT_KEY 0x00000000FFFFFFFFull
// iou>0.5 <=> inter > sum2/3. Certain-yes / certain-no thresholds with ~1e-3
// relative margin (total fp rounding incl. the +1 pre-add is <1e-5 relative).
#define C_HI 0.33350f
#define C_LO 0.33317f
#define TRI 4336                 // per-class warp-iters: S(16)=16*16^2+15*16
#define TT (KCLS * TRI)          // 351216
#define NBLK2 148
#define CH 149                   // ceil(TT / (NBLK2*16))

// Inter-kernel state (stream order provides all synchronization).
__device__ float    g_ss[KCLS * R];        // sorted scores
__device__ int      g_si[KCLS * R];        // sorted original roi indices
__device__ float4   g_box[KCLS * R];       // x1, y1, x2+1, y2+1 (hot loop)
__device__ float4   g_boxo[KCLS * R];      // original box (exact fixup)
__device__ float    g_area[KCLS * R];      // exact ref-association area
__device__ unsigned g_sup[KCLS * R * 16];  // wide suppression bits
__device__ unsigned g_unc[KCLS * 16];      // band-row flags
__device__ unsigned long long g_keys[R];   // per-roi (score, ~class) argmax keys

__device__ __forceinline__ void bbox_xform(const float* __restrict__ rois,
                                           const float* __restrict__ deltas,
                                           int r, int k,
                                           float& x1, float& y1,
                                           float& x2, float& y2) {
    float rx1 = rois[r * 4 + 0], ry1 = rois[r * 4 + 1];
    float rx2 = rois[r * 4 + 2], ry2 = rois[r * 4 + 3];
    float w = rx2 - rx1 + 1.0f, h = ry2 - ry1 + 1.0f;
    float cx = rx1 + 0.5f * w, cy = ry1 + 0.5f * h;
    const float* dp = deltas + r * (4 * KCLS) + k * 4;
    float dx = dp[0] / 10.0f;
    float dy = dp[1] / 10.0f;
    float dw = fminf(dp[2] / 5.0f, XFORM_CLIP);
    float dh = fminf(dp[3] / 5.0f, XFORM_CLIP);
    float pcx = dx * w + cx, pcy = dy * h + cy;
    float pw = expf(dw) * w, ph = expf(dh) * h;
    x1 = fminf(fmaxf(pcx - 0.5f * pw, 0.0f), IMW_M1);
    y1 = fminf(fmaxf(pcy - 0.5f * ph, 0.0f), IMH_M1);
    x2 = fminf(fmaxf(pcx + 0.5f * pw - 1.0f, 0.0f), IMW_M1);
    y2 = fminf(fmaxf(pcy + 0.5f * ph - 1.0f, 0.0f), IMH_M1);
}

// Hybrid bitonic sort of 512 (score desc, idx asc on ties). Values live in
// registers; smem arrays are scratch for the 10 cross-warp stages only.
__device__ __forceinline__ void bitonic_sort_512(float& rs, int& ri,
                                                 float* ss, int* si, int tid) {
    #pragma unroll
    for (int kk = 2; kk <= R; kk <<= 1) {
        int j = kk >> 1;
        for (; j >= 32; j >>= 1) {          // cross-warp: via smem
            ss[tid] = rs; si[tid] = ri;
            __syncthreads();
            int p = tid ^ j;
            float os = ss[p]; int oi = si[p];
            bool mineFirst = (rs > os) || (rs == os && ri < oi);
            bool up = ((tid & kk) == 0);
            bool iAmLow = ((tid & j) == 0);
            bool keepMine = (up == iAmLow) ? mineFirst : !mineFirst;
            if (!keepMine) { rs = os; ri = oi; }
            __syncthreads();
        }
        for (; j > 0; j >>= 1) {            // in-warp: via shfl
            float os = __shfl_xor_sync(0xFFFFFFFFu, rs, j);
            int   oi = __shfl_xor_sync(0xFFFFFFFFu, ri, j);
            bool mineFirst = (rs > os) || (rs == os && ri < oi);
            bool up = ((tid & kk) == 0);
            bool iAmLow = ((tid & j) == 0);
            bool keepMine = (up == iAmLow) ? mineFirst : !mineFirst;
            if (!keepMine) { rs = os; ri = oi; }
        }
    }
}

// ========================== K1: sort + transform ===========================
__global__ __launch_bounds__(R, 1)
void sort_xform_kernel(const float* __restrict__ rois,
                       const float* __restrict__ deltas,
                       const float* __restrict__ scores) {
    const int tid = threadIdx.x;
    const int bid = blockIdx.x;

    if (bid == KCLS) {          // init block
        g_keys[tid] = INIT_KEY;
        for (int t = tid; t < KCLS * 16; t += R) g_unc[t] = 0u;
        return;
    }

    __shared__ float ss[R];
    __shared__ int   si[R];
    const int k = bid;

    // Zero this class's suppression mask (K2 writes only the upper triangle).
    {
        uint4* z = (uint4*)&g_sup[k * R * 16];
        #pragma unroll
        for (int t = tid; t < R * 16 / 4; t += R) z[t] = make_uint4(0, 0, 0, 0);
    }

    float rs = scores[tid * KCLS + k];
    int   ri = tid;
    bitonic_sort_512(rs, ri, ss, si, tid);

    float x1, y1, x2, y2;
    bbox_xform(rois, deltas, ri, k, x1, y1, x2, y2);

    const int o = k * R + tid;
    g_ss[o]   = rs;
    g_si[o]   = ri;
    g_boxo[o] = make_float4(x1, y1, x2, y2);
    g_box[o]  = make_float4(x1, y1, x2 + 1.0f, y2 + 1.0f);
    g_area[o] = (x2 - x1 + 1.0f) * (y2 - y1 + 1.0f);
}

// ========================== K2: mask build (full chip) =====================
__global__ __launch_bounds__(R, 1)
void mask_kernel() {
    __shared__ float4 sB[2][R];
    __shared__ float  sA[2][R];

    const int tid  = threadIdx.x;
    const int lane = tid & 31;
    const int wid  = tid >> 5;
    const int b    = blockIdx.x;

    const int t0b = b * (16 * CH);
    if (t0b >= TT) return;
    const int t1b = min(t0b + 16 * CH, TT);
    const int c0  = t0b / TRI;
    const int c1  = (t1b - 1) / TRI;   // c1 - c0 <= 1 (block range 2384 < TRI)

    for (int cc = 0; cc <= c1 - c0; ++cc) {
        const int base = (c0 + cc) * R;
        sB[cc][tid] = g_box[base + tid];
        sA[cc][tid] = g_area[base + tid];
    }
    __syncthreads();

    int t  = t0b + wid * CH;
    int t1 = min(t + CH, t1b);

    while (t < t1) {
        const int c  = t / TRI;
        const int cc = c - c0;
        const int rr = t - c * TRI;
        const int cend = min(t1, (c + 1) * TRI);
        int jw = 0;
        while (16 * (jw + 1) * (jw + 1) + 15 * (jw + 1) <= rr) jw++;
        int i = rr - (16 * jw * jw + 15 * jw);
        unsigned myflags = 0u;
        unsigned* supc = &g_sup[c * (R * 16)];

        while (t < cend) {
            const int rows = (jw << 5) + 31;
            const int iend = min(rows, i + (cend - t));
            const int j = (jw << 5) + lane;
            const float4 jb = sB[cc][j];
            const float jarea = sA[cc][j];
            t += iend - i;
            for (; i < iend; ++i) {
                float4 bI = sB[cc][i];       // broadcast LDS128
                float aa = sA[cc][i];
                float xx1 = fmaxf(bI.x, jb.x);
                float yy1 = fmaxf(bI.y, jb.y);
                float xx2 = fminf(bI.z, jb.z);   // z,w carry the +1 already
                float yy2 = fminf(bI.w, jb.w);
                float iw = fmaxf(xx2 - xx1, 0.0f);
                float ih = fmaxf(yy2 - yy1, 0.0f);
                float inter = iw * ih;
                float sum2  = aa + jarea;
                bool jgt = (j > i);
                bool p_wide = (inter > C_LO * sum2) && jgt;
                bool p_unc  = p_wide && (inter <= C_HI * sum2);
                unsigned bits = __ballot_sync(0xFFFFFFFFu, p_wide);
                bool anyunc = __any_sync(0xFFFFFFFFu, p_unc);
                if (lane == 0) supc[i * 16 + jw] = bits;
                unsigned rowbit = (lane == (i >> 5)) ? (1u << (i & 31)) : 0u;
                myflags |= anyunc ? rowbit : 0u;
            }
            jw++; i = 0;
        }
        if (lane < 16 && myflags) atomicOr(&g_unc[c * 16 + lane], myflags);
    }
}

// ========================== K3: fixup + greedy + fold ======================
__global__ __launch_bounds__(R, 1)
void greedy_kernel() {
    const int c = blockIdx.x;
    if (c == 0) return;                       // cls_valid[0] = False
    if (!(g_ss[c * R] > 0.001f)) return;      // max score after sort

    __shared__ unsigned sup[R][16];
    __shared__ unsigned s_keep[16];

    const int tid  = threadIdx.x;
    const int lane = tid & 31;
    const int wid  = tid >> 5;

    // Bulk-load this class's mask into smem.
    {
        const uint4* src = (const uint4*)&g_sup[c * (R * 16)];
        uint4* dst = (uint4*)&sup[0][0];
        #pragma unroll
        for (int t = tid; t < R * 16 / 4; t += R) dst[t] = src[t];
    }
    __syncthreads();

    // Exact fixup of band rows (warp w handles flag word w), using original
    // boxes and the reference's exact association + div.rn.
    {
        unsigned f = g_unc[c * 16 + wid];
        const float4* bo = &g_boxo[c * R];
        const float*  ar = &g_area[c * R];
        while (f) {
            int bbit = __ffs(f) - 1; f &= f - 1;
            int i = (wid << 5) + bbit;
            float4 bi = bo[i];
            float  ai = ar[i];
            for (int jw2 = 0; jw2 < 16; ++jw2) {
                int j = (jw2 << 5) + lane;
                float4 jb = bo[j];
                float xx1 = fmaxf(bi.x, jb.x);
                float yy1 = fmaxf(bi.y, jb.y);
                float xx2 = fminf(bi.z, jb.z);
                float yy2 = fminf(bi.w, jb.w);
                float iw = fmaxf(xx2 - xx1 + 1.0f, 0.0f);
                float ih = fmaxf(yy2 - yy1 + 1.0f, 0.0f);
                float inter = iw * ih;
                float denom = (ai + ar[j]) - inter;
                float iou = inter / denom;            // exact div.rn as ref
                bool ov = (iou > 0.5f) && (j > i);
                unsigned bits = __ballot_sync(0xFFFFFFFFu, ov);
                if (lane == 0) sup[i][jw2] = bits;
            }
        }
    }
    __syncthreads();

    // Word-phase greedy (warp 0), early cap at POST_NMS_TOPN=300.
    if (wid == 0) {
        unsigned keepw = (lane < 16) ? 0xFFFFFFFFu : 0u;
        int cnt = 0;
        bool capped = false;
        for (int w = 0; w < 16 && !capped; ++w) {
            unsigned bw = __shfl_sync(0xFFFFFFFFu, keepw, w);
            while (bw) {
                int bb = __ffs(bw) - 1;
                int i = (w << 5) + bb;
                cnt++;
                if (cnt == 300) {
                    if (lane < 16 && lane > w) keepw = 0u;
                    if (lane == w) keepw &= ((2u << bb) - 1u);
                    capped = true;
                    break;
                }
                unsigned srl = sup[i][lane & 15];
                unsigned srw = sup[i][w];
                if (lane < 16) keepw &= ~srl;
                bw = (bw ^ (1u << bb)) & ~srw;
            }
        }
        if (lane < 16) s_keep[lane] = keepw;
    }
    __syncthreads();

    // Fold kept scores into global per-roi argmax keys:
    // key = (score_bits << 32) | (~class): max score wins, ties -> lowest class.
    {
        bool kept = (s_keep[tid >> 5] >> (tid & 31)) & 1u;
        if (kept) {
            unsigned long long key =
                ((unsigned long long)__float_as_uint(g_ss[c * R + tid]) << 32) |
                (unsigned long long)(0xFFFFFFFFu - (unsigned)c);
            atomicMax(&g_keys[g_si[c * R + tid]], key);
        }
    }
}

// ========================== K4: select + output ============================
__global__ __launch_bounds__(R, 1)
void select_kernel(const float* __restrict__ rois,
                   const float* __restrict__ deltas,
                   float* __restrict__ out) {
    __shared__ float ss[R];
    __shared__ int   si[R];
    __shared__ int   plbl[R];
    const int tid = threadIdx.x;

    float rs; int ri;
    {
        unsigned long long key = g_keys[tid];
        rs = __uint_as_float((unsigned)(key >> 32));
        plbl[tid] = (int)(0xFFFFFFFFu - (unsigned)(key & 0xFFFFFFFFull));
        ri = tid;
    }
    __syncthreads();

    bitonic_sort_512(rs, ri, ss, si, tid);

    if (tid < 100) {
        float sc = rs;
        int r   = ri;
        int lbl = plbl[r];
        bool valid = sc > 0.001f;

        float x1, y1, x2, y2;
        bbox_xform(rois, deltas, r, lbl, x1, y1, x2, y2);

        if (!valid) { sc = 0.0f; x1 = 0.0f; y1 = 0.0f; x2 = 0.0f; y2 = 0.0f; }

        out[tid * 5 + 0] = sc;
        out[tid * 5 + 1] = x1;
        out[tid * 5 + 2] = y1;
        out[tid * 5 + 3] = x2;
        out[tid * 5 + 4] = y2;
        out[500 + tid] = (float)lbl;
        out[600 + tid] = (float)r;
    }
}

extern "C" void kernel_launch(void* const* d_in, const int* in_sizes, int n_in,
                              void* d_out, int out_size) {
    const float* rois   = (const float*)d_in[0];
    const float* deltas = (const float*)d_in[1];
    const float* scores = (const float*)d_in[2];
    float* out = (float*)d_out;

    sort_xform_kernel<<<KCLS + 1, R>>>(rois, deltas, scores);
    mask_kernel<<<NBLK2, R>>>();
    greedy_kernel<<<KCLS, R>>>();
    select_kernel<<<1, R>>>(rois, deltas, out);
}

// round 9
// speedup vs baseline: 6.4784x; 1.0072x over previous
#include <cuda_runtime.h>
#include <math.h>

#define R 512
#define KCLS 81
#define XFORM_CLIP 4.135166556742356f
#define IMW_M1 1332.0f
#define IMH_M1 799.0f
#define INIT_KEY 0x00000000FFFFFFFFull
// iou>0.5 <=> inter > sum2/3. Certain-yes / certain-no thresholds with ~1e-3
// relative margin (total fp rounding incl. the +1 pre-add is <1e-5 relative).
#define C_HI 0.33350f
#define C_LO 0.33317f
#define TRI 4336                   // per-class triangle warp-iters
#define TT2 ((KCLS - 1) * TRI)     // classes 1..80 -> 346880
#define NBLK2 148
#define CH2 147                    // ceil(TT2 / (NBLK2*16))

// Inter-kernel state. g_sup's lower-triangle words are NEVER written: they
// stay at their zero initialization (deterministic across replays since K2
// writes only the input-determined upper triangle). g_unc accumulates the
// same flag bits every replay (atomicOr of a pure function of the input),
// so it is never cleared.
__device__ float    g_ss[KCLS * R];        // sorted scores
__device__ int      g_si[KCLS * R];        // sorted original roi indices
__device__ float4   g_box[KCLS * R];       // x1, y1, x2+1, y2+1 (hot loop)
__device__ float4   g_boxo[KCLS * R];      // original box (exact fixup)
__device__ float    g_area[KCLS * R];      // exact ref-association area
__device__ unsigned g_sup[KCLS * R * 16];  // wide suppression bits
__device__ unsigned g_unc[KCLS * 16];      // band-row flags (sticky)
__device__ unsigned long long g_keys[R];   // per-roi (score, ~class) keys
__device__ int g_ctr;                      // finished greedy blocks

__device__ __forceinline__ void bbox_xform(const float* __restrict__ rois,
                                           const float* __restrict__ deltas,
                                           int r, int k,
                                           float& x1, float& y1,
                                           float& x2, float& y2) {
    float rx1 = rois[r * 4 + 0], ry1 = rois[r * 4 + 1];
    float rx2 = rois[r * 4 + 2], ry2 = rois[r * 4 + 3];
    float w = rx2 - rx1 + 1.0f, h = ry2 - ry1 + 1.0f;
    float cx = rx1 + 0.5f * w, cy = ry1 + 0.5f * h;
    const float* dp = deltas + r * (4 * KCLS) + k * 4;
    float dx = dp[0] / 10.0f;
    float dy = dp[1] / 10.0f;
    float dw = fminf(dp[2] / 5.0f, XFORM_CLIP);
    float dh = fminf(dp[3] / 5.0f, XFORM_CLIP);
    float pcx = dx * w + cx, pcy = dy * h + cy;
    float pw = expf(dw) * w, ph = expf(dh) * h;
    x1 = fminf(fmaxf(pcx - 0.5f * pw, 0.0f), IMW_M1);
    y1 = fminf(fmaxf(pcy - 0.5f * ph, 0.0f), IMH_M1);
    x2 = fminf(fmaxf(pcx + 0.5f * pw - 1.0f, 0.0f), IMW_M1);
    y2 = fminf(fmaxf(pcy + 0.5f * ph - 1.0f, 0.0f), IMH_M1);
}

// Hybrid bitonic sort of 512 (score desc, idx asc on ties).
__device__ __forceinline__ void bitonic_sort_512(float& rs, int& ri,
                                                 float* ss, int* si, int tid) {
    #pragma unroll
    for (int kk = 2; kk <= R; kk <<= 1) {
        int j = kk >> 1;
        for (; j >= 32; j >>= 1) {          // cross-warp: via smem
            ss[tid] = rs; si[tid] = ri;
            __syncthreads();
            int p = tid ^ j;
            float os = ss[p]; int oi = si[p];
            bool mineFirst = (rs > os) || (rs == os && ri < oi);
            bool up = ((tid & kk) == 0);
            bool iAmLow = ((tid & j) == 0);
            bool keepMine = (up == iAmLow) ? mineFirst : !mineFirst;
            if (!keepMine) { rs = os; ri = oi; }
            __syncthreads();
        }
        for (; j > 0; j >>= 1) {            // in-warp: via shfl
            float os = __shfl_xor_sync(0xFFFFFFFFu, rs, j);
            int   oi = __shfl_xor_sync(0xFFFFFFFFu, ri, j);
            bool mineFirst = (rs > os) || (rs == os && ri < oi);
            bool up = ((tid & kk) == 0);
            bool iAmLow = ((tid & j) == 0);
            bool keepMine = (up == iAmLow) ? mineFirst : !mineFirst;
            if (!keepMine) { rs = os; ri = oi; }
        }
    }
}

// ========================== K1: sort + transform ===========================
// Block 0 = g_keys init (class 0 is never consumed); blocks 1..80 = classes.
__global__ __launch_bounds__(R, 1)
void sort_xform_kernel(const float* __restrict__ rois,
                       const float* __restrict__ deltas,
                       const float* __restrict__ scores) {
    const int tid = threadIdx.x;
    const int k   = blockIdx.x;

    if (k == 0) {
        g_keys[tid] = INIT_KEY;
        return;
    }

    __shared__ float ss[R];
    __shared__ int   si[R];

    float rs = scores[tid * KCLS + k];
    int   ri = tid;
    bitonic_sort_512(rs, ri, ss, si, tid);

    float x1, y1, x2, y2;
    bbox_xform(rois, deltas, ri, k, x1, y1, x2, y2);

    const int o = k * R + tid;
    g_ss[o]   = rs;
    g_si[o]   = ri;
    g_boxo[o] = make_float4(x1, y1, x2, y2);
    g_box[o]  = make_float4(x1, y1, x2 + 1.0f, y2 + 1.0f);
    g_area[o] = (x2 - x1 + 1.0f) * (y2 - y1 + 1.0f);
}

// ========================== K2: mask build (full chip, classes 1..80) ======
__global__ __launch_bounds__(R, 1)
void mask_kernel() {
    __shared__ float4 sB[2][R];
    __shared__ float  sA[2][R];

    const int tid  = threadIdx.x;
    const int lane = tid & 31;
    const int wid  = tid >> 5;
    const int b    = blockIdx.x;

    const int t0b = b * (16 * CH2);
    if (t0b >= TT2) return;
    const int t1b = min(t0b + 16 * CH2, TT2);
    const int c0  = 1 + t0b / TRI;
    const int c1  = 1 + (t1b - 1) / TRI;   // c1 - c0 <= 1 (block span < TRI)

    for (int cc = 0; cc <= c1 - c0; ++cc) {
        const int base = (c0 + cc) * R;
        sB[cc][tid] = g_box[base + tid];
        sA[cc][tid] = g_area[base + tid];
    }
    __syncthreads();

    int t  = t0b + wid * CH2;
    int t1 = min(t + CH2, t1b);

    while (t < t1) {
        const int c  = 1 + t / TRI;
        const int cc = c - c0;
        const int rr = t - (c - 1) * TRI;
        const int cend = min(t1, (c - 1 + 1) * TRI);
        int jw = 0;
        while (16 * (jw + 1) * (jw + 1) + 15 * (jw + 1) <= rr) jw++;
        int i = rr - (16 * jw * jw + 15 * jw);
        unsigned myflags = 0u;
        unsigned* supc = &g_sup[c * (R * 16)];

        while (t < cend) {
            const int rows = (jw << 5) + 31;
            const int iend = min(rows, i + (cend - t));
            const int j = (jw << 5) + lane;
            const float4 jb = sB[cc][j];
            const float jarea = sA[cc][j];
            t += iend - i;
            const int iendA = min(iend, jw << 5);
            // Full-word rows: every lane has j > i, no predicate needed.
            for (; i < iendA; ++i) {
                float4 bI = sB[cc][i];       // broadcast LDS128
                float aa = sA[cc][i];
                float xx1 = fmaxf(bI.x, jb.x);
                float yy1 = fmaxf(bI.y, jb.y);
                float xx2 = fminf(bI.z, jb.z);   // z,w carry the +1 already
                float yy2 = fminf(bI.w, jb.w);
                float iw = fmaxf(xx2 - xx1, 0.0f);
                float ih = fmaxf(yy2 - yy1, 0.0f);
                float inter = iw * ih;
                float sum2  = aa + jarea;
                bool p_wide = (inter > C_LO * sum2);
                bool p_unc  = p_wide && (inter <= C_HI * sum2);
                unsigned bits = __ballot_sync(0xFFFFFFFFu, p_wide);
                bool anyunc = __any_sync(0xFFFFFFFFu, p_unc);
                if (lane == 0) supc[i * 16 + jw] = bits;
                unsigned rowbit = (lane == (i >> 5)) ? (1u << (i & 31)) : 0u;
                myflags |= anyunc ? rowbit : 0u;
            }
            // Boundary rows (i within this word): mask j > i.
            for (; i < iend; ++i) {
                float4 bI = sB[cc][i];
                float aa = sA[cc][i];
                float xx1 = fmaxf(bI.x, jb.x);
                float yy1 = fmaxf(bI.y, jb.y);
                float xx2 = fminf(bI.z, jb.z);
                float yy2 = fminf(bI.w, jb.w);
                float iw = fmaxf(xx2 - xx1, 0.0f);
                float ih = fmaxf(yy2 - yy1, 0.0f);
                float inter = iw * ih;
                float sum2  = aa + jarea;
                bool jgt = (j > i);
                bool p_wide = (inter > C_LO * sum2) && jgt;
                bool p_unc  = p_wide && (inter <= C_HI * sum2);
                unsigned bits = __ballot_sync(0xFFFFFFFFu, p_wide);
                bool anyunc = __any_sync(0xFFFFFFFFu, p_unc);
                if (lane == 0) supc[i * 16 + jw] = bits;
                unsigned rowbit = (lane == (i >> 5)) ? (1u << (i & 31)) : 0u;
                myflags |= anyunc ? rowbit : 0u;
            }
            jw++; i = 0;
        }
        if (lane < 16 && myflags) atomicOr(&g_unc[c * 16 + lane], myflags);
    }
}

// ================= K3: fixup + greedy + fold + (block 81) select ===========
__global__ __launch_bounds__(R, 1)
void greedy_select_kernel(const float* __restrict__ rois,
                          const float* __restrict__ deltas,
                          float* __restrict__ out) {
    __shared__ unsigned sup[R][16];
    __shared__ unsigned s_keep[16];

    const int tid  = threadIdx.x;
    const int lane = tid & 31;
    const int wid  = tid >> 5;
    const int c    = blockIdx.x;

    if (c < KCLS) {
        // ---------------- greedy block (one class) ----------------
        if (c == 0 || !(g_ss[c * R] > 0.001f)) {
            if (tid == 0) { __threadfence(); atomicAdd(&g_ctr, 1); }
            return;
        }

        // Bulk-load this class's mask into smem (lower-triangle words are the
        // never-written zero-initialized globals).
        {
            const uint4* src = (const uint4*)&g_sup[c * (R * 16)];
            uint4* dst = (uint4*)&sup[0][0];
            #pragma unroll
            for (int t = tid; t < R * 16 / 4; t += R) dst[t] = src[t];
        }
        __syncthreads();

        // Exact fixup of band rows (warp w handles flag word w).
        {
            unsigned f = g_unc[c * 16 + wid];
            const float4* bo = &g_boxo[c * R];
            const float*  ar = &g_area[c * R];
            while (f) {
                int bbit = __ffs(f) - 1; f &= f - 1;
                int i = (wid << 5) + bbit;
                float4 bi = bo[i];
                float  ai = ar[i];
                for (int jw2 = 0; jw2 < 16; ++jw2) {
                    int j = (jw2 << 5) + lane;
                    float4 jb = bo[j];
                    float xx1 = fmaxf(bi.x, jb.x);
                    float yy1 = fmaxf(bi.y, jb.y);
                    float xx2 = fminf(bi.z, jb.z);
                    float yy2 = fminf(bi.w, jb.w);
                    float iw = fmaxf(xx2 - xx1 + 1.0f, 0.0f);
                    float ih = fmaxf(yy2 - yy1 + 1.0f, 0.0f);
                    float inter = iw * ih;
                    float denom = (ai + ar[j]) - inter;
                    float iou = inter / denom;            // exact div.rn
                    bool ov = (iou > 0.5f) && (j > i);
                    unsigned bits = __ballot_sync(0xFFFFFFFFu, ov);
                    if (lane == 0) sup[i][jw2] = bits;
                }
            }
        }
        __syncthreads();

        // Word-phase greedy (warp 0), early cap at POST_NMS_TOPN=300.
        if (wid == 0) {
            unsigned keepw = (lane < 16) ? 0xFFFFFFFFu : 0u;
            int cnt = 0;
            bool capped = false;
            for (int w = 0; w < 16 && !capped; ++w) {
                unsigned bw = __shfl_sync(0xFFFFFFFFu, keepw, w);
                while (bw) {
                    int bb = __ffs(bw) - 1;
                    int i = (w << 5) + bb;
                    cnt++;
                    if (cnt == 300) {
                        if (lane < 16 && lane > w) keepw = 0u;
                        if (lane == w) keepw &= ((2u << bb) - 1u);
                        capped = true;
                        break;
                    }
                    unsigned srl = sup[i][lane & 15];
                    unsigned srw = sup[i][w];
                    if (lane < 16) keepw &= ~srl;
                    bw = (bw ^ (1u << bb)) & ~srw;
                }
            }
            if (lane < 16) s_keep[lane] = keepw;
        }
        __syncthreads();

        // Fold kept scores into global per-roi argmax keys.
        {
            bool kept = (s_keep[tid >> 5] >> (tid & 31)) & 1u;
            if (kept) {
                unsigned long long key =
                    ((unsigned long long)__float_as_uint(g_ss[c * R + tid]) << 32) |
                    (unsigned long long)(0xFFFFFFFFu - (unsigned)c);
                atomicMax(&g_keys[g_si[c * R + tid]], key);
            }
        }
        __threadfence();
        __syncthreads();
        if (tid == 0) atomicAdd(&g_ctr, 1);

    } else {
        // ---------------- select block (rank-by-count) ----------------
        if (tid == 0) {
            while (*(volatile int*)&g_ctr < KCLS) {}
        }
        __syncthreads();
        __threadfence();

        unsigned long long* keys = (unsigned long long*)&sup[0][0];

        // Own roi = tid. Build comparison key (score desc, roi asc).
        unsigned long long myk;
        int lbl;
        float sc;
        {
            unsigned long long g = *(volatile unsigned long long*)&g_keys[tid];
            unsigned sbits = (unsigned)(g >> 32);
            sc  = __uint_as_float(sbits);
            lbl = (int)(0xFFFFFFFFu - (unsigned)(g & 0xFFFFFFFFull));
            myk = ((unsigned long long)sbits << 32) |
                  (unsigned long long)(R - 1 - tid);
            keys[tid] = myk;
        }
        __syncthreads();

        // Rank = #{keys strictly greater} (all keys distinct by construction).
        int rank = 0;
        #pragma unroll 8
        for (int j = 0; j < R; ++j)
            rank += (keys[j] > myk);

        if (rank < 100) {
            bool valid = sc > 0.001f;
            float x1, y1, x2, y2;
            bbox_xform(rois, deltas, tid, lbl, x1, y1, x2, y2);
            if (!valid) { sc = 0.0f; x1 = 0.0f; y1 = 0.0f; x2 = 0.0f; y2 = 0.0f; }

            out[rank * 5 + 0] = sc;
            out[rank * 5 + 1] = x1;
            out[rank * 5 + 2] = y1;
            out[rank * 5 + 3] = x2;
            out[rank * 5 + 4] = y2;
            out[500 + rank] = (float)lbl;
            out[600 + rank] = (float)tid;
        }
        __syncthreads();
        if (tid == 0) g_ctr = 0;   // rearm for next replay
    }
}

extern "C" void kernel_launch(void* const* d_in, const int* in_sizes, int n_in,
                              void* d_out, int out_size) {
    const float* rois   = (const float*)d_in[0];
    const float* deltas = (const float*)d_in[1];
    const float* scores = (const float*)d_in[2];
    float* out = (float*)d_out;

    sort_xform_kernel<<<KCLS, R>>>(rois, deltas, scores);
    mask_kernel<<<NBLK2, R>>>();
    greedy_select_kernel<<<KCLS + 1, R>>>(rois, deltas, out);
}

// round 11
// speedup vs baseline: 8.1980x; 1.2654x over previous
#include <cuda_runtime.h>
#include <math.h>

#define R 512
#define KCLS 81
#define XFORM_CLIP 4.135166556742356f
#define IMW_M1 1332.0f
#define IMH_M1 799.0f
#define INIT_KEY 0x00000000FFFFFFFFull
// iou>0.5 <=> inter > sum2/3. Certain-yes / certain-no thresholds with ~1e-3
// relative margin (total fp rounding incl. the +1 pre-add is <1e-5 relative).
#define C_HI 0.33350f
#define C_LO 0.33317f
#define TPC 136                    // 32x32 tiles per class triangle
#define TTILES ((KCLS - 1) * TPC)  // 10880
#define NBLK2 148
#define CHT 74                     // ceil(TTILES / NBLK2)

// Inter-kernel state. g_T words beyond each row's own word index are NEVER
// written: they stay zero-initialized (deterministic: K2 writes only the
// input-determined triangle, identically every replay). g_unc accumulates
// the same flag bits every replay (atomicOr of a pure function of input).
__device__ float    g_ss[KCLS * R];        // sorted scores
__device__ int      g_si[KCLS * R];        // sorted original roi indices
__device__ float4   g_box[KCLS * R];       // x1, y1, x2+1, y2+1 (hot loop)
__device__ float4   g_boxo[KCLS * R];      // original box (exact fixup)
__device__ float    g_area[KCLS * R];      // exact ref-association area
__device__ unsigned g_T[KCLS * R * 16];    // transposed mask: T[p] = suppressors q<p
__device__ unsigned g_unc[KCLS * 16];      // band-column flags (sticky)
__device__ unsigned long long g_keys[R];   // per-roi (score, ~class) keys
__device__ int g_ctr;                      // finished greedy blocks

__device__ __forceinline__ void bbox_xform(const float* __restrict__ rois,
                                           const float* __restrict__ deltas,
                                           int r, int k,
                                           float& x1, float& y1,
                                           float& x2, float& y2) {
    float rx1 = rois[r * 4 + 0], ry1 = rois[r * 4 + 1];
    float rx2 = rois[r * 4 + 2], ry2 = rois[r * 4 + 3];
    float w = rx2 - rx1 + 1.0f, h = ry2 - ry1 + 1.0f;
    float cx = rx1 + 0.5f * w, cy = ry1 + 0.5f * h;
    const float* dp = deltas + r * (4 * KCLS) + k * 4;
    float dx = dp[0] / 10.0f;
    float dy = dp[1] / 10.0f;
    float dw = fminf(dp[2] / 5.0f, XFORM_CLIP);
    float dh = fminf(dp[3] / 5.0f, XFORM_CLIP);
    float pcx = dx * w + cx, pcy = dy * h + cy;
    float pw = expf(dw) * w, ph = expf(dh) * h;
    x1 = fminf(fmaxf(pcx - 0.5f * pw, 0.0f), IMW_M1);
    y1 = fminf(fmaxf(pcy - 0.5f * ph, 0.0f), IMH_M1);
    x2 = fminf(fmaxf(pcx + 0.5f * pw - 1.0f, 0.0f), IMW_M1);
    y2 = fminf(fmaxf(pcy + 0.5f * ph - 1.0f, 0.0f), IMH_M1);
}

// ========================== K1: rank sort + transform ======================
// Block 0 = g_keys init; blocks 1..80 = classes. Stable descending order via
// 64-bit key (softmax scores are positive -> float bits are uint-monotone).
__global__ __launch_bounds__(R, 1)
void sort_xform_kernel(const float* __restrict__ rois,
                       const float* __restrict__ deltas,
                       const float* __restrict__ scores) {
    const int tid = threadIdx.x;
    const int k   = blockIdx.x;

    if (k == 0) {
        g_keys[tid] = INIT_KEY;
        return;
    }

    __shared__ unsigned long long keys[R];

    float s = scores[tid * KCLS + k];
    unsigned long long mykey =
        ((unsigned long long)__float_as_uint(s) << 32) |
        (unsigned long long)(R - 1 - tid);
    keys[tid] = mykey;
    __syncthreads();

    int rank = 0;
    const ulonglong2* k2 = (const ulonglong2*)keys;
    #pragma unroll 8
    for (int q = 0; q < R / 2; ++q) {      // broadcast LDS.128, conflict-free
        ulonglong2 v = k2[q];
        rank += (v.x > mykey) + (v.y > mykey);
    }

    float x1, y1, x2, y2;
    bbox_xform(rois, deltas, tid, k, x1, y1, x2, y2);   // own roi

    const int o = k * R + rank;
    g_ss[o]   = s;
    g_si[o]   = tid;
    g_boxo[o] = make_float4(x1, y1, x2, y2);
    g_box[o]  = make_float4(x1, y1, x2 + 1.0f, y2 + 1.0f);
    g_area[o] = (x2 - x1 + 1.0f) * (y2 - y1 + 1.0f);
}

// ========================== K2: transposed mask build ======================
// Tile (jw, iw): columns j = jw*32+lane, rows i = iw*32+ii (i < j only).
// Lane j accumulates its column's 32 bits in a register -> 1 coalesced STG.
__global__ __launch_bounds__(R, 1)
void mask_kernel() {
    __shared__ float4 sB[2][R];
    __shared__ float  sA[2][R];

    const int tid  = threadIdx.x;
    const int lane = tid & 31;
    const int wid  = tid >> 5;
    const int b    = blockIdx.x;

    const int t0 = b * CHT;
    if (t0 >= TTILES) return;
    const int t1 = min(t0 + CHT, TTILES);
    const int c0 = 1 + t0 / TPC;
    const int c1 = 1 + (t1 - 1) / TPC;     // c1 - c0 <= 1

    for (int cc = 0; cc <= c1 - c0; ++cc) {
        const int base = (c0 + cc) * R;
        sB[cc][tid] = g_box[base + tid];
        sA[cc][tid] = g_area[base + tid];
    }
    __syncthreads();

    for (int tile = t0 + wid; tile < t1; tile += 16) {
        const int c  = 1 + tile / TPC;
        const int tt = tile - (c - 1) * TPC;
        int jw = 0;
        while ((jw + 1) * (jw + 2) / 2 <= tt) jw++;
        const int iw = tt - jw * (jw + 1) / 2;
        const int cc = c - c0;

        const int j = (jw << 5) + lane;
        const float4 jb = sB[cc][j];
        const float  ja = sA[cc][j];
        const int ibase = iw << 5;

        unsigned bits = 0u;
        bool anyU = false;

        if (iw < jw) {
            #pragma unroll 4
            for (int ii = 0; ii < 32; ++ii) {
                float4 bI = sB[cc][ibase + ii];   // broadcast LDS128
                float aa  = sA[cc][ibase + ii];
                float xx1 = fmaxf(bI.x, jb.x);
                float yy1 = fmaxf(bI.y, jb.y);
                float xx2 = fminf(bI.z, jb.z);    // z,w carry the +1 already
                float yy2 = fminf(bI.w, jb.w);
                float iwd = fmaxf(xx2 - xx1, 0.0f);
                float ihd = fmaxf(yy2 - yy1, 0.0f);
                float inter = iwd * ihd;
                float sum2  = aa + ja;
                bool pw = (inter > C_LO * sum2);
                bits |= pw ? (1u << ii) : 0u;
                anyU |= pw && (inter <= C_HI * sum2);
            }
        } else {                                   // diagonal tile: need i<j
            #pragma unroll 4
            for (int ii = 0; ii < 32; ++ii) {
                float4 bI = sB[cc][ibase + ii];
                float aa  = sA[cc][ibase + ii];
                float xx1 = fmaxf(bI.x, jb.x);
                float yy1 = fmaxf(bI.y, jb.y);
                float xx2 = fminf(bI.z, jb.z);
                float yy2 = fminf(bI.w, jb.w);
                float iwd = fmaxf(xx2 - xx1, 0.0f);
                float ihd = fmaxf(yy2 - yy1, 0.0f);
                float inter = iwd * ihd;
                float sum2  = aa + ja;
                bool pw = (inter > C_LO * sum2) && (ii < lane);
                bits |= pw ? (1u << ii) : 0u;
                anyU |= pw && (inter <= C_HI * sum2);
            }
        }

        g_T[c * (R * 16) + j * 16 + iw] = bits;    // coalesced-ish STG.32
        unsigned uw = __ballot_sync(0xFFFFFFFFu, anyU);
        if (lane == 0 && uw) atomicOr(&g_unc[c * 16 + jw], uw);
    }
}

// ============ K3: fixup + Jacobi NMS + fold + (block 81) select ============
__global__ __launch_bounds__(R, 1)
void greedy_select_kernel(const float* __restrict__ rois,
                          const float* __restrict__ deltas,
                          float* __restrict__ out) {
    const int tid  = threadIdx.x;
    const int lane = tid & 31;
    const int wid  = tid >> 5;
    const int c    = blockIdx.x;

    if (c < KCLS) {
        // ---------------- per-class NMS block ----------------
        if (c == 0 || !(g_ss[c * R] > 0.001f)) {
            if (tid == 0) { __threadfence(); atomicAdd(&g_ctr, 1); }
            return;
        }

        __shared__ unsigned ka[16], kb[16];

        // Exact fixup of flagged band columns (warp w scans flag word w).
        {
            unsigned f = g_unc[c * 16 + wid];
            const float4* bo = &g_boxo[c * R];
            const float*  ar = &g_area[c * R];
            while (f) {
                int bbit = __ffs(f) - 1; f &= f - 1;
                int j = (wid << 5) + bbit;
                float4 bj = bo[j];
                float  aj = ar[j];
                for (int w2 = 0; w2 < 16; ++w2) {
                    int q = (w2 << 5) + lane;
                    float4 bq = bo[q];
                    float xx1 = fmaxf(bq.x, bj.x);
                    float yy1 = fmaxf(bq.y, bj.y);
                    float xx2 = fminf(bq.z, bj.z);
                    float yy2 = fminf(bq.w, bj.w);
                    float iwd = fmaxf(xx2 - xx1 + 1.0f, 0.0f);
                    float ihd = fmaxf(yy2 - yy1 + 1.0f, 0.0f);
                    float inter = iwd * ihd;
                    float denom = (ar[q] + aj) - inter;
                    float iou = inter / denom;            // exact div.rn
                    bool ov = (iou > 0.5f) && (q < j);
                    unsigned bits = __ballot_sync(0xFFFFFFFFu, ov);
                    if (lane == 0) g_T[c * (R * 16) + j * 16 + w2] = bits;
                }
            }
        }
        if (tid < 16) ka[tid] = 0xFFFFFFFFu;
        __syncthreads();   // fixup gmem writes visible block-wide

        // Load own T row (suppressors of sorted position p = tid) to regs.
        const unsigned* tr = &g_T[c * (R * 16) + tid * 16];
        uint4 T0 = *(const uint4*)(tr + 0);
        uint4 T1 = *(const uint4*)(tr + 4);
        uint4 T2 = *(const uint4*)(tr + 8);
        uint4 T3 = *(const uint4*)(tr + 12);

        // Jacobi fixpoint: keep[p] = !(exists kept suppressor q<p).
        // Unchanged pass == unique fixpoint == sequential greedy result.
        unsigned* cur = ka;
        unsigned* nxt = kb;
        while (true) {
            unsigned sup =
                (cur[0]  & T0.x) | (cur[1]  & T0.y) | (cur[2]  & T0.z) | (cur[3]  & T0.w) |
                (cur[4]  & T1.x) | (cur[5]  & T1.y) | (cur[6]  & T1.z) | (cur[7]  & T1.w) |
                (cur[8]  & T2.x) | (cur[9]  & T2.y) | (cur[10] & T2.z) | (cur[11] & T2.w) |
                (cur[12] & T3.x) | (cur[13] & T3.y) | (cur[14] & T3.z) | (cur[15] & T3.w);
            unsigned word = __ballot_sync(0xFFFFFFFFu, sup == 0u);
            bool chg = false;
            if (lane == 0) {
                nxt[wid] = word;
                chg = (word != cur[wid]);
            }
            if (!__syncthreads_or(chg)) break;
            unsigned* t = cur; cur = nxt; nxt = t;
        }

        // POST_NMS_TOPN cap (first 300 kept in sorted order) + fold.
        {
            unsigned* fin = nxt;   // after the non-changing pass, nxt == cur content
            int w = tid >> 5;
            int pre = 0;
            for (int q = 0; q < w; ++q) pre += __popc(fin[q]);
            pre += __popc(fin[w] & ((1u << (tid & 31)) - 1u));
            bool kept = ((fin[w] >> (tid & 31)) & 1u) && (pre < 300);
            if (kept) {
                unsigned long long key =
                    ((unsigned long long)__float_as_uint(g_ss[c * R + tid]) << 32) |
                    (unsigned long long)(0xFFFFFFFFu - (unsigned)c);
                atomicMax(&g_keys[g_si[c * R + tid]], key);
            }
        }
        __threadfence();
        __syncthreads();
        if (tid == 0) atomicAdd(&g_ctr, 1);

    } else {
        // ---------------- select block (rank-by-count) ----------------
        __shared__ unsigned long long keys[R];

        if (tid == 0) {
            while (*(volatile int*)&g_ctr < KCLS) {}
        }
        __syncthreads();
        __threadfence();

        unsigned long long myk;
        int lbl;
        float sc;
        {
            unsigned long long g = *(volatile unsigned long long*)&g_keys[tid];
            unsigned sbits = (unsigned)(g >> 32);
            sc  = __uint_as_float(sbits);
            lbl = (int)(0xFFFFFFFFu - (unsigned)(g & 0xFFFFFFFFull));
            myk = ((unsigned long long)sbits << 32) |
                  (unsigned long long)(R - 1 - tid);
            keys[tid] = myk;
        }
        __syncthreads();

        int rank = 0;
        const ulonglong2* k2 = (const ulonglong2*)keys;
        #pragma unroll 8
        for (int q = 0; q < R / 2; ++q) {
            ulonglong2 v = k2[q];
            rank += (v.x > myk) + (v.y > myk);
        }

        if (rank < 100) {
            bool valid = sc > 0.001f;
            float x1, y1, x2, y2;
            bbox_xform(rois, deltas, tid, lbl, x1, y1, x2, y2);
            if (!valid) { sc = 0.0f; x1 = 0.0f; y1 = 0.0f; x2 = 0.0f; y2 = 0.0f; }

            out[rank * 5 + 0] = sc;
            out[rank * 5 + 1] = x1;
            out[rank * 5 + 2] = y1;
            out[rank * 5 + 3] = x2;
            out[rank * 5 + 4] = y2;
            out[500 + rank] = (float)lbl;
            out[600 + rank] = (float)tid;
        }
        __syncthreads();
        if (tid == 0) g_ctr = 0;   // rearm for next replay
    }
}

extern "C" void kernel_launch(void* const* d_in, const int* in_sizes, int n_in,
                              void* d_out, int out_size) {
    const float* rois   = (const float*)d_in[0];
    const float* deltas = (const float*)d_in[1];
    const float* scores = (const float*)d_in[2];
    float* out = (float*)d_out;

    sort_xform_kernel<<<KCLS, R>>>(rois, deltas, scores);
    mask_kernel<<<NBLK2, R>>>();
    greedy_select_kernel<<<KCLS + 1, R>>>(rois, deltas, out);
}